// round 3
// baseline (speedup 1.0000x reference)
#include <cuda_runtime.h>

#define S_LEN 4096
#define BATCH 2
#define EMB   1024
#define HEADS 8
#define HD    128
#define WINW  256
#define SPAD  (S_LEN + 2*WINW)   // 4608

// Scratch in attention-friendly layout:
//  g_Q: (b',h,s',d)            b' in [0,2), h in [0,8), s' in [0,4096), d in [0,128)
//  g_K/g_V: (b',h,jpad,d)      jpad in [0,4608) with ±256 zero pad rows
__device__ float g_Q[BATCH*HEADS*S_LEN*HD];
__device__ float g_K[BATCH*HEADS*SPAD*HD];
__device__ float g_V[BATCH*HEADS*SPAD*HD];

// ---------------------------------------------------------------------------
// Zero the pad rows of K/V (rows [0,256) and [4352,4608) per (b',h))
// ---------------------------------------------------------------------------
__global__ void zero_pads_kernel()
{
    int i = blockIdx.x * blockDim.x + threadIdx.x;
    const int total = BATCH*HEADS * (2*WINW) * HD;   // 16*512*128 = 1048576
    if (i >= total) return;
    int d  = i & (HD-1);
    int t  = i >> 7;
    int jr = t & (2*WINW - 1);      // 0..511
    int bh = t >> 9;                // 0..15
    int jpad = (jr < WINW) ? jr : (S_LEN + jr);   // [0,256) or [4352,4608)
    int off = (bh*SPAD + jpad)*HD + d;
    g_K[off] = 0.0f;
    g_V[off] = 0.0f;
}

// ---------------------------------------------------------------------------
// Fused QKV projection: out = X @ W^T + bias, X[r][k] = val[s*2048 + b*1024 + k]
// with r = b*4096+s.  blockIdx.z selects {q,k,v}.
// Epilogue applies the .view() scramble: b' = r&1, s' = r>>1, and writes into
// g_Q (scaled) or g_K/g_V (offset by WINW pad rows).
// ---------------------------------------------------------------------------
__global__ __launch_bounds__(256) void qkv_gemm_kernel(
    const float* __restrict__ val,
    const float* __restrict__ Wq, const float* __restrict__ bq,
    const float* __restrict__ Wk, const float* __restrict__ bk,
    const float* __restrict__ Wv, const float* __restrict__ bv)
{
    __shared__ float As[8][128];
    __shared__ float Bs[8][128];

    const int mat = blockIdx.z;
    const float* W   = (mat == 0) ? Wq : (mat == 1 ? Wk : Wv);
    const float* bia = (mat == 0) ? bq : (mat == 1 ? bk : bv);

    const int row0 = blockIdx.y * 128;
    const int col0 = blockIdx.x * 128;
    const int tid  = threadIdx.x;

    // load mapping: each thread loads one float4 of A and one of B per k-tile
    const int lm = tid >> 1;             // 0..127
    const int lk = (tid & 1) * 4;        // 0 or 4
    const int rA = row0 + lm;
    const int bb = rA >> 12;
    const int ss = rA & 4095;
    const float* xrow = val + ss*2048 + bb*1024;
    const float* wrow = W + (size_t)(col0 + lm) * 1024;

    const int trow = (tid >> 4) * 8;     // 0..120
    const int tcol = (tid & 15) * 8;     // 0..120

    float acc[8][8];
    #pragma unroll
    for (int i = 0; i < 8; i++)
        #pragma unroll
        for (int j = 0; j < 8; j++) acc[i][j] = 0.0f;

    for (int k0 = 0; k0 < 1024; k0 += 8) {
        float4 a4 = *(const float4*)(xrow + k0 + lk);
        float4 b4 = *(const float4*)(wrow + k0 + lk);
        __syncthreads();
        As[lk+0][lm] = a4.x; As[lk+1][lm] = a4.y; As[lk+2][lm] = a4.z; As[lk+3][lm] = a4.w;
        Bs[lk+0][lm] = b4.x; Bs[lk+1][lm] = b4.y; Bs[lk+2][lm] = b4.z; Bs[lk+3][lm] = b4.w;
        __syncthreads();
        #pragma unroll
        for (int kk = 0; kk < 8; kk++) {
            float ra[8], rb[8];
            *(float4*)&ra[0] = *(const float4*)&As[kk][trow];
            *(float4*)&ra[4] = *(const float4*)&As[kk][trow+4];
            *(float4*)&rb[0] = *(const float4*)&Bs[kk][tcol];
            *(float4*)&rb[4] = *(const float4*)&Bs[kk][tcol+4];
            #pragma unroll
            for (int i = 0; i < 8; i++)
                #pragma unroll
                for (int j = 0; j < 8; j++)
                    acc[i][j] = fmaf(ra[i], rb[j], acc[i][j]);
        }
    }

    const float scale = 0.08838834764831845f;  // 1/sqrt(128)
    #pragma unroll
    for (int i = 0; i < 8; i++) {
        int r  = row0 + trow + i;
        int bp = r & 1;
        int sp = r >> 1;
        #pragma unroll
        for (int jj = 0; jj < 2; jj++) {
            int e0 = col0 + tcol + jj*4;
            float4 o;
            o.x = acc[i][jj*4+0] + bia[e0+0];
            o.y = acc[i][jj*4+1] + bia[e0+1];
            o.z = acc[i][jj*4+2] + bia[e0+2];
            o.w = acc[i][jj*4+3] + bia[e0+3];
            int h  = e0 >> 7;
            int dd = e0 & 127;
            if (mat == 0) {
                o.x *= scale; o.y *= scale; o.z *= scale; o.w *= scale;
                float* dst = g_Q + ((bp*HEADS + h)*S_LEN + sp)*HD + dd;
                *(float4*)dst = o;
            } else {
                float* base = (mat == 1) ? g_K : g_V;
                float* dst = base + ((bp*HEADS + h)*SPAD + (sp + WINW))*HD + dd;
                *(float4*)dst = o;
            }
        }
    }
}

// ---------------------------------------------------------------------------
// Banded flash attention. Block = 64 queries of one (b',h); 8 warps x 8 queries.
// Query s' attends padded keys jpad in [s', s'+512]; keys outside the band are
// masked to -inf (excluded), padded rows give score 0 / value 0 (included).
// ---------------------------------------------------------------------------
__global__ __launch_bounds__(256) void attn_kernel(float* __restrict__ out)
{
    extern __shared__ float sm[];
    float* Qs = sm;                         // [64][128]
    float* Kt = sm + 64*128;                // [128][33]  (transposed, padded)
    float* Vs = Kt + 128*33;                // [32][132]  (row-padded)

    const int s0   = blockIdx.x * 64;
    const int h    = blockIdx.y;
    const int bp   = blockIdx.z;
    const int tid  = threadIdx.x;
    const int wid  = tid >> 5;
    const int lane = tid & 31;
    const int bh   = bp*HEADS + h;

    const float* Qg = g_Q + (bh*S_LEN + s0)*HD;
    const float* Kg = g_K + (bh*SPAD + s0)*HD;
    const float* Vg = g_V + (bh*SPAD + s0)*HD;

    // Load Q tile (64x128 floats)
    for (int i = tid; i < 64*32; i += 256)
        ((float4*)Qs)[i] = ((const float4*)Qg)[i];

    const int qbase = wid * 8;

    float m[8], l[8], pv[8], acc[8][4];
    #pragma unroll
    for (int q = 0; q < 8; q++) {
        m[q] = -1e30f; l[q] = 0.0f;
        acc[q][0] = acc[q][1] = acc[q][2] = acc[q][3] = 0.0f;
    }

    // keys union for this tile: jpad in [s0, s0+576) -> 18 chunks of 32
    for (int c = 0; c < 18; c++) {
        const int j0 = c * 32;
        __syncthreads();
        for (int i = tid; i < 32*128; i += 256) {
            int k = i >> 7;
            int d = i & 127;
            Kt[d*33 + k]  = Kg[(j0 + k)*128 + d];
            Vs[k*132 + d] = Vg[(j0 + k)*128 + d];
        }
        __syncthreads();

        // ---- scores: lane = key (j0+lane), 8 queries per warp ----
        float sc[8] = {0,0,0,0,0,0,0,0};
        #pragma unroll 4
        for (int d4 = 0; d4 < 32; d4++) {
            const int d = d4 * 4;
            const float kv0 = Kt[(d+0)*33 + lane];
            const float kv1 = Kt[(d+1)*33 + lane];
            const float kv2 = Kt[(d+2)*33 + lane];
            const float kv3 = Kt[(d+3)*33 + lane];
            #pragma unroll
            for (int q = 0; q < 8; q++) {
                const float4 qv = *(const float4*)&Qs[(qbase+q)*128 + d];
                float s = sc[q];
                s = fmaf(qv.x, kv0, s);
                s = fmaf(qv.y, kv1, s);
                s = fmaf(qv.z, kv2, s);
                s = fmaf(qv.w, kv3, s);
                sc[q] = s;
            }
        }

        // ---- online softmax update per query ----
        const int jpad = s0 + j0 + lane;
        #pragma unroll
        for (int q = 0; q < 8; q++) {
            const int sq = s0 + qbase + q;
            const bool valid = (jpad >= sq) && (jpad <= sq + 2*WINW);
            float sv = valid ? sc[q] : -1e30f;
            float mx = sv;
            #pragma unroll
            for (int off = 16; off > 0; off >>= 1)
                mx = fmaxf(mx, __shfl_xor_sync(0xffffffffu, mx, off));
            const float mnew = fmaxf(m[q], mx);
            const float p = valid ? __expf(sv - mnew) : 0.0f;
            float su = p;
            #pragma unroll
            for (int off = 16; off > 0; off >>= 1)
                su += __shfl_xor_sync(0xffffffffu, su, off);
            const float alpha = __expf(m[q] - mnew);
            m[q] = mnew;
            l[q] = l[q]*alpha + su;
            acc[q][0] *= alpha; acc[q][1] *= alpha;
            acc[q][2] *= alpha; acc[q][3] *= alpha;
            pv[q] = p;
        }

        // ---- AV: lane owns dims [lane*4, lane*4+4) ----
        #pragma unroll 4
        for (int k = 0; k < 32; k++) {
            const float4 vv = *(const float4*)&Vs[k*132 + lane*4];
            #pragma unroll
            for (int q = 0; q < 8; q++) {
                const float pk = __shfl_sync(0xffffffffu, pv[q], k);
                acc[q][0] = fmaf(pk, vv.x, acc[q][0]);
                acc[q][1] = fmaf(pk, vv.y, acc[q][1]);
                acc[q][2] = fmaf(pk, vv.z, acc[q][2]);
                acc[q][3] = fmaf(pk, vv.w, acc[q][3]);
            }
        }
    }

    // ---- write out: out[s'][b'][h*128+dd] ----
    #pragma unroll
    for (int q = 0; q < 8; q++) {
        const int sq = s0 + qbase + q;
        const float inv = 1.0f / l[q];
        float4 o;
        o.x = acc[q][0]*inv; o.y = acc[q][1]*inv;
        o.z = acc[q][2]*inv; o.w = acc[q][3]*inv;
        *(float4*)&out[(size_t)sq*2048 + bp*1024 + h*128 + lane*4] = o;
    }
}

// ---------------------------------------------------------------------------
extern "C" void kernel_launch(void* const* d_in, const int* in_sizes, int n_in,
                              void* d_out, int out_size)
{
    (void)in_sizes; (void)n_in; (void)out_size;
    const float* val = (const float*)d_in[0];
    const float* Wq  = (const float*)d_in[1];
    const float* bq  = (const float*)d_in[2];
    const float* Wk  = (const float*)d_in[3];
    const float* bk  = (const float*)d_in[4];
    const float* Wv  = (const float*)d_in[5];
    const float* bv  = (const float*)d_in[6];
    float* out = (float*)d_out;

    const int smem_bytes = (64*128 + 128*33 + 32*132) * 4;   // 66560
    cudaFuncSetAttribute(attn_kernel, cudaFuncAttributeMaxDynamicSharedMemorySize,
                         smem_bytes);

    {
        const int total = BATCH*HEADS * (2*WINW) * HD;
        zero_pads_kernel<<<(total + 255)/256, 256>>>();
    }
    {
        dim3 grid(EMB/128, (BATCH*S_LEN)/128, 3);
        qkv_gemm_kernel<<<grid, 256>>>(val, Wq, bq, Wk, bk, Wv, bv);
    }
    {
        dim3 grid(S_LEN/64, HEADS, BATCH);
        attn_kernel<<<grid, 256, smem_bytes>>>(out);
    }
}

// round 7
// speedup vs baseline: 1.7335x; 1.7335x over previous
#include <cuda_runtime.h>
#include <cuda_bf16.h>
#include <cstdint>
#include <cstddef>

#define S_LEN 4096
#define BATCH 2
#define EMB   1024
#define HEADS 8
#define HD    128
#define WINW  256
#define SPAD  (S_LEN + 2*WINW)   // 4608

// Attention-layout scratch
__device__ float g_Q[BATCH*HEADS*S_LEN*HD];
__device__ float g_K[BATCH*HEADS*SPAD*HD];
__device__ float g_V[BATCH*HEADS*SPAD*HD];

// Split-bf16 operands
__device__ __align__(16) __nv_bfloat16 g_Xh[8192*1024];
__device__ __align__(16) __nv_bfloat16 g_Xl[8192*1024];
__device__ __align__(16) __nv_bfloat16 g_Wh[3*1024*1024];
__device__ __align__(16) __nv_bfloat16 g_Wl[3*1024*1024];

// ---------------------------------------------------------------------------
// helpers
// ---------------------------------------------------------------------------
__device__ __forceinline__ uint32_t smem_to_u32(const void* p) {
    uint32_t a;
    asm("{ .reg .u64 t; cvta.to.shared.u64 t, %1; cvt.u32.u64 %0, t; }"
        : "=r"(a) : "l"(p));
    return a;
}
__device__ __forceinline__ void cp_async16(uint32_t dst, const void* src) {
    asm volatile("cp.async.cg.shared.global [%0], [%1], 16;"
                 :: "r"(dst), "l"(src) : "memory");
}
#define CP_COMMIT() asm volatile("cp.async.commit_group;" ::: "memory")
#define CP_WAIT0()  asm volatile("cp.async.wait_group 0;" ::: "memory")
#define CP_WAIT1()  asm volatile("cp.async.wait_group 1;" ::: "memory")

__device__ __forceinline__ void ldmatrix_x4(uint32_t* r, uint32_t addr) {
    asm volatile("ldmatrix.sync.aligned.m8n8.x4.shared.b16 {%0,%1,%2,%3}, [%4];"
                 : "=r"(r[0]), "=r"(r[1]), "=r"(r[2]), "=r"(r[3]) : "r"(addr));
}
__device__ __forceinline__ void mma16816(float* c, const uint32_t* a,
                                         const uint32_t* b) {
    asm volatile(
        "mma.sync.aligned.m16n8k16.row.col.f32.bf16.bf16.f32 "
        "{%0,%1,%2,%3}, {%4,%5,%6,%7}, {%8,%9}, {%0,%1,%2,%3};"
        : "+f"(c[0]), "+f"(c[1]), "+f"(c[2]), "+f"(c[3])
        : "r"(a[0]), "r"(a[1]), "r"(a[2]), "r"(a[3]), "r"(b[0]), "r"(b[1]));
}

// ---------------------------------------------------------------------------
// Split fp32 -> (bf16 hi, bf16 lo). X rows are the view-scramble gather.
// ---------------------------------------------------------------------------
__global__ void convert_x_kernel(const float* __restrict__ val)
{
    int i = blockIdx.x * blockDim.x + threadIdx.x;
    if (i >= 8192*1024) return;
    int r = i >> 10, k = i & 1023;
    int b = r >> 12, s = r & 4095;
    float f = val[s*2048 + b*1024 + k];
    __nv_bfloat16 h = __float2bfloat16(f);
    g_Xh[i] = h;
    g_Xl[i] = __float2bfloat16(f - __bfloat162float(h));
}

__global__ void convert_w_kernel(const float* __restrict__ Wq,
                                 const float* __restrict__ Wk,
                                 const float* __restrict__ Wv)
{
    int i = blockIdx.x * blockDim.x + threadIdx.x;
    if (i >= 3*1024*1024) return;
    int mat = i >> 20;
    const float* W = (mat == 0) ? Wq : (mat == 1 ? Wk : Wv);
    float f = W[i & 0xFFFFF];
    __nv_bfloat16 h = __float2bfloat16(f);
    g_Wh[i] = h;
    g_Wl[i] = __float2bfloat16(f - __bfloat162float(h));
}

// ---------------------------------------------------------------------------
// Zero the pad rows of K/V
// ---------------------------------------------------------------------------
__global__ void zero_pads_kernel()
{
    int i = blockIdx.x * blockDim.x + threadIdx.x;
    const int total = BATCH*HEADS * (2*WINW) * HD;
    if (i >= total) return;
    int d  = i & (HD-1);
    int t  = i >> 7;
    int jr = t & (2*WINW - 1);
    int bh = t >> 9;
    int jpad = (jr < WINW) ? jr : (S_LEN + jr);
    int off = (bh*SPAD + jpad)*HD + d;
    g_K[off] = 0.0f;
    g_V[off] = 0.0f;
}

// ---------------------------------------------------------------------------
// Warp-MMA GEMM: C[8192x1024] = X @ W^T + bias (3 matrices via blockIdx.z)
// CTA 128x128, K-tile 32, cp.async double buffer, split-bf16 (3 products).
// ---------------------------------------------------------------------------
#define BK 32
#define NKT 32                    // 1024 / 32
#define LDSTR 40                  // smem row stride in bf16 (80 B)
#define VAR_BYTES (128*LDSTR*2)   // 10240
#define STAGE_BYTES (4*VAR_BYTES) // 40960: [Ah, Al, Bh, Bl]
#define GEMM_SMEM (2*STAGE_BYTES) // 81920

__global__ __launch_bounds__(256) void qkv_mma_kernel(
    const float* __restrict__ bq, const float* __restrict__ bk,
    const float* __restrict__ bv)
{
    extern __shared__ char smem[];
    const uint32_t smem_base = smem_to_u32(smem);
    const int tid  = threadIdx.x;
    const int wid  = tid >> 5;
    const int lane = tid & 31;

    const int col0 = blockIdx.x * 128;
    const int row0 = blockIdx.y * 128;
    const int mat  = blockIdx.z;
    const float* bia = (mat == 0) ? bq : (mat == 1 ? bk : bv);

    const __nv_bfloat16* Wh = g_Wh + (size_t)mat * 1048576;
    const __nv_bfloat16* Wl = g_Wl + (size_t)mat * 1048576;

    // per-thread load slots: 2 chunks per variant (512 chunks of 16B each)
    const int ch0_row = tid >> 2,         ch0_quad = tid & 3;
    const int ch1_row = (tid + 256) >> 2, ch1_quad = (tid + 256) & 3;

    const __nv_bfloat16* srcs[4] = { g_Xh, g_Xl, Wh, Wl };
    const int vrow0[4] = { row0, row0, col0, col0 };

    // warp layout: 4 m-warps x 2 n-warps; warp tile 32 x 64
    const int warp_m0 = (wid & 3) * 32;
    const int warp_n0 = (wid >> 2) * 64;

    // ldmatrix lane offsets
    const int offA_row = (lane & 7) + (lane & 8);      // 0..15
    const int offA_k   = (lane & 16) >> 1;             // 0 or 8
    const int offB_row = (lane & 7) + ((lane & 16) >> 1);
    const int offB_k   = lane & 8;

    float acc[2][8][4];
    #pragma unroll
    for (int mt = 0; mt < 2; mt++)
        #pragma unroll
        for (int nf = 0; nf < 8; nf++)
            acc[mt][nf][0] = acc[mt][nf][1] = acc[mt][nf][2] = acc[mt][nf][3] = 0.f;

    // prefetch tile 0
    {
        const uint32_t sb = smem_base;
        #pragma unroll
        for (int v = 0; v < 4; v++) {
            cp_async16(sb + v*VAR_BYTES + (ch0_row*LDSTR + ch0_quad*8)*2,
                       srcs[v] + (size_t)(vrow0[v] + ch0_row)*1024 + ch0_quad*8);
            cp_async16(sb + v*VAR_BYTES + (ch1_row*LDSTR + ch1_quad*8)*2,
                       srcs[v] + (size_t)(vrow0[v] + ch1_row)*1024 + ch1_quad*8);
        }
        CP_COMMIT();
    }

    for (int kt = 0; kt < NKT; kt++) {
        if (kt + 1 < NKT) {
            const uint32_t sb = smem_base + ((kt+1) & 1) * STAGE_BYTES;
            const int k0 = (kt+1) * BK;
            #pragma unroll
            for (int v = 0; v < 4; v++) {
                cp_async16(sb + v*VAR_BYTES + (ch0_row*LDSTR + ch0_quad*8)*2,
                           srcs[v] + (size_t)(vrow0[v] + ch0_row)*1024 + k0 + ch0_quad*8);
                cp_async16(sb + v*VAR_BYTES + (ch1_row*LDSTR + ch1_quad*8)*2,
                           srcs[v] + (size_t)(vrow0[v] + ch1_row)*1024 + k0 + ch1_quad*8);
            }
            CP_COMMIT();
            CP_WAIT1();
        } else {
            CP_WAIT0();
        }
        __syncthreads();

        const uint32_t sb = smem_base + (kt & 1) * STAGE_BYTES;
        const uint32_t aH = sb, aL = sb + VAR_BYTES;
        const uint32_t bH = sb + 2*VAR_BYTES, bL = sb + 3*VAR_BYTES;

        #pragma unroll
        for (int ks = 0; ks < 2; ks++) {
            const int kk = ks * 16;
            uint32_t ahf[2][4], alf[2][4];
            #pragma unroll
            for (int mt = 0; mt < 2; mt++) {
                const uint32_t ro = (uint32_t)((warp_m0 + mt*16 + offA_row)*LDSTR
                                               + kk + offA_k) * 2;
                ldmatrix_x4(ahf[mt], aH + ro);
                ldmatrix_x4(alf[mt], aL + ro);
            }
            #pragma unroll
            for (int np = 0; np < 4; np++) {
                uint32_t bh4[4], bl4[4];
                const uint32_t ro = (uint32_t)((warp_n0 + np*16 + offB_row)*LDSTR
                                               + kk + offB_k) * 2;
                ldmatrix_x4(bh4, bH + ro);
                ldmatrix_x4(bl4, bL + ro);
                #pragma unroll
                for (int mt = 0; mt < 2; mt++) {
                    mma16816(acc[mt][2*np],   ahf[mt], &bh4[0]);
                    mma16816(acc[mt][2*np],   ahf[mt], &bl4[0]);
                    mma16816(acc[mt][2*np],   alf[mt], &bh4[0]);
                    mma16816(acc[mt][2*np+1], ahf[mt], &bh4[2]);
                    mma16816(acc[mt][2*np+1], ahf[mt], &bl4[2]);
                    mma16816(acc[mt][2*np+1], alf[mt], &bh4[2]);
                }
            }
        }
        __syncthreads();
    }

    // ---- epilogue: bias (+Q scale), view-scramble scatter ----
    const float scale = 0.08838834764831845f;   // 1/sqrt(128)
    #pragma unroll
    for (int mt = 0; mt < 2; mt++) {
        #pragma unroll
        for (int nf = 0; nf < 8; nf++) {
            const int col = col0 + warp_n0 + nf*8 + (lane & 3)*2;
            const int h   = col >> 7;
            const int dd  = col & 127;
            const float b0 = bia[col], b1 = bia[col+1];
            #pragma unroll
            for (int half = 0; half < 2; half++) {
                const int r  = row0 + warp_m0 + mt*16 + (lane >> 2) + half*8;
                const int bp = r & 1;
                const int sp = r >> 1;
                float v0 = acc[mt][nf][half*2+0] + b0;
                float v1 = acc[mt][nf][half*2+1] + b1;
                float* dst;
                if (mat == 0) {
                    v0 *= scale; v1 *= scale;
                    dst = g_Q + ((size_t)(bp*HEADS + h)*S_LEN + sp)*HD + dd;
                } else {
                    float* base = (mat == 1) ? g_K : g_V;
                    dst = base + ((size_t)(bp*HEADS + h)*SPAD + (sp + WINW))*HD + dd;
                }
                float2 o; o.x = v0; o.y = v1;
                *(float2*)dst = o;
            }
        }
    }
}

// ---------------------------------------------------------------------------
// Banded flash attention (unchanged from passing round)
// ---------------------------------------------------------------------------
__global__ __launch_bounds__(256) void attn_kernel(float* __restrict__ out)
{
    extern __shared__ float sm[];
    float* Qs = sm;                         // [64][128]
    float* Kt = sm + 64*128;                // [128][33]
    float* Vs = Kt + 128*33;                // [32][132]

    const int s0   = blockIdx.x * 64;
    const int h    = blockIdx.y;
    const int bp   = blockIdx.z;
    const int tid  = threadIdx.x;
    const int wid  = tid >> 5;
    const int lane = tid & 31;
    const int bh   = bp*HEADS + h;

    const float* Qg = g_Q + (size_t)(bh*S_LEN + s0)*HD;
    const float* Kg = g_K + (size_t)(bh*SPAD + s0)*HD;
    const float* Vg = g_V + (size_t)(bh*SPAD + s0)*HD;

    for (int i = tid; i < 64*32; i += 256)
        ((float4*)Qs)[i] = ((const float4*)Qg)[i];

    const int qbase = wid * 8;

    float m[8], l[8], pv[8], acc[8][4];
    #pragma unroll
    for (int q = 0; q < 8; q++) {
        m[q] = -1e30f; l[q] = 0.0f;
        acc[q][0] = acc[q][1] = acc[q][2] = acc[q][3] = 0.0f;
    }

    for (int c = 0; c < 18; c++) {
        const int j0 = c * 32;
        __syncthreads();
        for (int i = tid; i < 32*128; i += 256) {
            int k = i >> 7;
            int d = i & 127;
            Kt[d*33 + k]  = Kg[(j0 + k)*128 + d];
            Vs[k*132 + d] = Vg[(j0 + k)*128 + d];
        }
        __syncthreads();

        float sc[8] = {0,0,0,0,0,0,0,0};
        #pragma unroll 4
        for (int d4 = 0; d4 < 32; d4++) {
            const int d = d4 * 4;
            const float kv0 = Kt[(d+0)*33 + lane];
            const float kv1 = Kt[(d+1)*33 + lane];
            const float kv2 = Kt[(d+2)*33 + lane];
            const float kv3 = Kt[(d+3)*33 + lane];
            #pragma unroll
            for (int q = 0; q < 8; q++) {
                const float4 qv = *(const float4*)&Qs[(qbase+q)*128 + d];
                float s = sc[q];
                s = fmaf(qv.x, kv0, s);
                s = fmaf(qv.y, kv1, s);
                s = fmaf(qv.z, kv2, s);
                s = fmaf(qv.w, kv3, s);
                sc[q] = s;
            }
        }

        const int jpad = s0 + j0 + lane;
        #pragma unroll
        for (int q = 0; q < 8; q++) {
            const int sq = s0 + qbase + q;
            const bool valid = (jpad >= sq) && (jpad <= sq + 2*WINW);
            float sv = valid ? sc[q] : -1e30f;
            float mx = sv;
            #pragma unroll
            for (int off = 16; off > 0; off >>= 1)
                mx = fmaxf(mx, __shfl_xor_sync(0xffffffffu, mx, off));
            const float mnew = fmaxf(m[q], mx);
            const float p = valid ? __expf(sv - mnew) : 0.0f;
            float su = p;
            #pragma unroll
            for (int off = 16; off > 0; off >>= 1)
                su += __shfl_xor_sync(0xffffffffu, su, off);
            const float alpha = __expf(m[q] - mnew);
            m[q] = mnew;
            l[q] = l[q]*alpha + su;
            acc[q][0] *= alpha; acc[q][1] *= alpha;
            acc[q][2] *= alpha; acc[q][3] *= alpha;
            pv[q] = p;
        }

        #pragma unroll 4
        for (int k = 0; k < 32; k++) {
            const float4 vv = *(const float4*)&Vs[k*132 + lane*4];
            #pragma unroll
            for (int q = 0; q < 8; q++) {
                const float pk = __shfl_sync(0xffffffffu, pv[q], k);
                acc[q][0] = fmaf(pk, vv.x, acc[q][0]);
                acc[q][1] = fmaf(pk, vv.y, acc[q][1]);
                acc[q][2] = fmaf(pk, vv.z, acc[q][2]);
                acc[q][3] = fmaf(pk, vv.w, acc[q][3]);
            }
        }
    }

    #pragma unroll
    for (int q = 0; q < 8; q++) {
        const int sq = s0 + qbase + q;
        const float inv = 1.0f / l[q];
        float4 o;
        o.x = acc[q][0]*inv; o.y = acc[q][1]*inv;
        o.z = acc[q][2]*inv; o.w = acc[q][3]*inv;
        *(float4*)&out[(size_t)sq*2048 + bp*1024 + h*128 + lane*4] = o;
    }
}

// ---------------------------------------------------------------------------
extern "C" void kernel_launch(void* const* d_in, const int* in_sizes, int n_in,
                              void* d_out, int out_size)
{
    (void)in_sizes; (void)n_in; (void)out_size;
    const float* val = (const float*)d_in[0];
    const float* Wq  = (const float*)d_in[1];
    const float* bq  = (const float*)d_in[2];
    const float* Wk  = (const float*)d_in[3];
    const float* bk  = (const float*)d_in[4];
    const float* Wv  = (const float*)d_in[5];
    const float* bv  = (const float*)d_in[6];
    float* out = (float*)d_out;

    const int attn_smem = (64*128 + 128*33 + 32*132) * 4;   // 66560
    cudaFuncSetAttribute(attn_kernel, cudaFuncAttributeMaxDynamicSharedMemorySize,
                         attn_smem);
    cudaFuncSetAttribute(qkv_mma_kernel, cudaFuncAttributeMaxDynamicSharedMemorySize,
                         GEMM_SMEM);

    convert_x_kernel<<<(8192*1024)/256, 256>>>(val);
    convert_w_kernel<<<(3*1024*1024)/256, 256>>>(Wq, Wk, Wv);
    {
        const int total = BATCH*HEADS * (2*WINW) * HD;
        zero_pads_kernel<<<(total + 255)/256, 256>>>();
    }
    {
        dim3 grid(1024/128, 8192/128, 3);
        qkv_mma_kernel<<<grid, 256, GEMM_SMEM>>>(bq, bk, bv);
    }
    {
        dim3 grid(S_LEN/64, HEADS, BATCH);
        attn_kernel<<<grid, 256, attn_smem>>>(out);
    }
}

// round 9
// speedup vs baseline: 2.7891x; 1.6090x over previous
#include <cuda_runtime.h>
#include <cuda_bf16.h>
#include <cstdint>
#include <cstddef>

#define S_LEN 4096
#define BATCH 2
#define EMB   1024
#define HEADS 8
#define HD    128
#define WINW  256
#define SPAD  (S_LEN + 2*WINW)   // 4608

// Split-bf16 Q/K/V in attention layout (written by GEMM epilogue)
__device__ __align__(16) __nv_bfloat16 g_Qh[BATCH*HEADS*S_LEN*HD];
__device__ __align__(16) __nv_bfloat16 g_Ql[BATCH*HEADS*S_LEN*HD];
__device__ __align__(16) __nv_bfloat16 g_Kh[BATCH*HEADS*SPAD*HD];
__device__ __align__(16) __nv_bfloat16 g_Kl[BATCH*HEADS*SPAD*HD];
__device__ __align__(16) __nv_bfloat16 g_Vh[BATCH*HEADS*SPAD*HD];
__device__ __align__(16) __nv_bfloat16 g_Vl[BATCH*HEADS*SPAD*HD];

// Split-bf16 GEMM inputs
__device__ __align__(16) __nv_bfloat16 g_Xh[8192*1024];
__device__ __align__(16) __nv_bfloat16 g_Xl[8192*1024];
__device__ __align__(16) __nv_bfloat16 g_Wh[3*1024*1024];
__device__ __align__(16) __nv_bfloat16 g_Wl[3*1024*1024];

// ---------------------------------------------------------------------------
// helpers
// ---------------------------------------------------------------------------
__device__ __forceinline__ uint32_t smem_to_u32(const void* p) {
    uint32_t a;
    asm("{ .reg .u64 t; cvta.to.shared.u64 t, %1; cvt.u32.u64 %0, t; }"
        : "=r"(a) : "l"(p));
    return a;
}
__device__ __forceinline__ void cp_async16(uint32_t dst, const void* src) {
    asm volatile("cp.async.cg.shared.global [%0], [%1], 16;"
                 :: "r"(dst), "l"(src) : "memory");
}
#define CP_COMMIT() asm volatile("cp.async.commit_group;" ::: "memory")
#define CP_WAIT0()  asm volatile("cp.async.wait_group 0;" ::: "memory")
#define CP_WAIT1()  asm volatile("cp.async.wait_group 1;" ::: "memory")

__device__ __forceinline__ void ldmatrix_x4(uint32_t* r, uint32_t addr) {
    asm volatile("ldmatrix.sync.aligned.m8n8.x4.shared.b16 {%0,%1,%2,%3}, [%4];"
                 : "=r"(r[0]), "=r"(r[1]), "=r"(r[2]), "=r"(r[3]) : "r"(addr));
}
__device__ __forceinline__ void ldmatrix_x4_trans(uint32_t* r, uint32_t addr) {
    asm volatile("ldmatrix.sync.aligned.m8n8.x4.trans.shared.b16 {%0,%1,%2,%3}, [%4];"
                 : "=r"(r[0]), "=r"(r[1]), "=r"(r[2]), "=r"(r[3]) : "r"(addr));
}
__device__ __forceinline__ void mma16816(float* c, const uint32_t* a,
                                         const uint32_t* b) {
    asm volatile(
        "mma.sync.aligned.m16n8k16.row.col.f32.bf16.bf16.f32 "
        "{%0,%1,%2,%3}, {%4,%5,%6,%7}, {%8,%9}, {%0,%1,%2,%3};"
        : "+f"(c[0]), "+f"(c[1]), "+f"(c[2]), "+f"(c[3])
        : "r"(a[0]), "r"(a[1]), "r"(a[2]), "r"(a[3]), "r"(b[0]), "r"(b[1]));
}
// pack two floats into bf16x2 (lo -> low half, hi -> high half)
__device__ __forceinline__ uint32_t pack_bf16x2(float lo, float hi) {
    uint32_t r;
    asm("cvt.rn.bf16x2.f32 %0, %1, %2;" : "=r"(r) : "f"(hi), "f"(lo));
    return r;
}

// ---------------------------------------------------------------------------
// Split fp32 -> (bf16 hi, bf16 lo). X rows are the view-scramble gather.
// ---------------------------------------------------------------------------
__global__ void convert_x_kernel(const float* __restrict__ val)
{
    int i = blockIdx.x * blockDim.x + threadIdx.x;
    if (i >= 8192*1024) return;
    int r = i >> 10, k = i & 1023;
    int b = r >> 12, s = r & 4095;
    float f = val[s*2048 + b*1024 + k];
    __nv_bfloat16 h = __float2bfloat16(f);
    g_Xh[i] = h;
    g_Xl[i] = __float2bfloat16(f - __bfloat162float(h));
}

__global__ void convert_w_kernel(const float* __restrict__ Wq,
                                 const float* __restrict__ Wk,
                                 const float* __restrict__ Wv)
{
    int i = blockIdx.x * blockDim.x + threadIdx.x;
    if (i >= 3*1024*1024) return;
    int mat = i >> 20;
    const float* W = (mat == 0) ? Wq : (mat == 1 ? Wk : Wv);
    float f = W[i & 0xFFFFF];
    __nv_bfloat16 h = __float2bfloat16(f);
    g_Wh[i] = h;
    g_Wl[i] = __float2bfloat16(f - __bfloat162float(h));
}

// ---------------------------------------------------------------------------
// Zero the pad rows of K/V (bf16 split arrays)
// ---------------------------------------------------------------------------
__global__ void zero_pads_kernel()
{
    int i = blockIdx.x * blockDim.x + threadIdx.x;
    const int total = BATCH*HEADS * (2*WINW) * HD;
    if (i >= total) return;
    int d  = i & (HD-1);
    int t  = i >> 7;
    int jr = t & (2*WINW - 1);
    int bh = t >> 9;
    int jpad = (jr < WINW) ? jr : (S_LEN + jr);
    size_t off = ((size_t)bh*SPAD + jpad)*HD + d;
    __nv_bfloat16 z = __float2bfloat16(0.0f);
    g_Kh[off] = z; g_Kl[off] = z;
    g_Vh[off] = z; g_Vl[off] = z;
}

// ---------------------------------------------------------------------------
// Warp-MMA GEMM: C[8192x1024] = X @ W^T + bias (3 matrices via blockIdx.z)
// Epilogue writes split-bf16 Q/K/V with view-scramble scatter.
// ---------------------------------------------------------------------------
#define BK 32
#define NKT 32                    // 1024 / 32
#define LDSTR 40                  // smem row stride in bf16 (80 B)
#define VAR_BYTES (128*LDSTR*2)   // 10240
#define STAGE_BYTES (4*VAR_BYTES) // 40960: [Ah, Al, Bh, Bl]
#define GEMM_SMEM (2*STAGE_BYTES) // 81920

__global__ __launch_bounds__(256) void qkv_mma_kernel(
    const float* __restrict__ bq, const float* __restrict__ bk,
    const float* __restrict__ bv)
{
    extern __shared__ char smem[];
    const uint32_t smem_base = smem_to_u32(smem);
    const int tid  = threadIdx.x;
    const int wid  = tid >> 5;
    const int lane = tid & 31;

    const int col0 = blockIdx.x * 128;
    const int row0 = blockIdx.y * 128;
    const int mat  = blockIdx.z;
    const float* bia = (mat == 0) ? bq : (mat == 1 ? bk : bv);

    const __nv_bfloat16* Wh = g_Wh + (size_t)mat * 1048576;
    const __nv_bfloat16* Wl = g_Wl + (size_t)mat * 1048576;

    const int ch0_row = tid >> 2,         ch0_quad = tid & 3;
    const int ch1_row = (tid + 256) >> 2, ch1_quad = (tid + 256) & 3;

    const __nv_bfloat16* srcs[4] = { g_Xh, g_Xl, Wh, Wl };
    const int vrow0[4] = { row0, row0, col0, col0 };

    const int warp_m0 = (wid & 3) * 32;
    const int warp_n0 = (wid >> 2) * 64;

    const int offA_row = (lane & 7) + (lane & 8);
    const int offA_k   = (lane & 16) >> 1;
    const int offB_row = (lane & 7) + ((lane & 16) >> 1);
    const int offB_k   = lane & 8;

    float acc[2][8][4];
    #pragma unroll
    for (int mt = 0; mt < 2; mt++)
        #pragma unroll
        for (int nf = 0; nf < 8; nf++)
            acc[mt][nf][0] = acc[mt][nf][1] = acc[mt][nf][2] = acc[mt][nf][3] = 0.f;

    {
        const uint32_t sb = smem_base;
        #pragma unroll
        for (int v = 0; v < 4; v++) {
            cp_async16(sb + v*VAR_BYTES + (ch0_row*LDSTR + ch0_quad*8)*2,
                       srcs[v] + (size_t)(vrow0[v] + ch0_row)*1024 + ch0_quad*8);
            cp_async16(sb + v*VAR_BYTES + (ch1_row*LDSTR + ch1_quad*8)*2,
                       srcs[v] + (size_t)(vrow0[v] + ch1_row)*1024 + ch1_quad*8);
        }
        CP_COMMIT();
    }

    for (int kt = 0; kt < NKT; kt++) {
        if (kt + 1 < NKT) {
            const uint32_t sb = smem_base + ((kt+1) & 1) * STAGE_BYTES;
            const int k0 = (kt+1) * BK;
            #pragma unroll
            for (int v = 0; v < 4; v++) {
                cp_async16(sb + v*VAR_BYTES + (ch0_row*LDSTR + ch0_quad*8)*2,
                           srcs[v] + (size_t)(vrow0[v] + ch0_row)*1024 + k0 + ch0_quad*8);
                cp_async16(sb + v*VAR_BYTES + (ch1_row*LDSTR + ch1_quad*8)*2,
                           srcs[v] + (size_t)(vrow0[v] + ch1_row)*1024 + k0 + ch1_quad*8);
            }
            CP_COMMIT();
            CP_WAIT1();
        } else {
            CP_WAIT0();
        }
        __syncthreads();

        const uint32_t sb = smem_base + (kt & 1) * STAGE_BYTES;
        const uint32_t aH = sb, aL = sb + VAR_BYTES;
        const uint32_t bH = sb + 2*VAR_BYTES, bL = sb + 3*VAR_BYTES;

        #pragma unroll
        for (int ks = 0; ks < 2; ks++) {
            const int kk = ks * 16;
            uint32_t ahf[2][4], alf[2][4];
            #pragma unroll
            for (int mt = 0; mt < 2; mt++) {
                const uint32_t ro = (uint32_t)((warp_m0 + mt*16 + offA_row)*LDSTR
                                               + kk + offA_k) * 2;
                ldmatrix_x4(ahf[mt], aH + ro);
                ldmatrix_x4(alf[mt], aL + ro);
            }
            #pragma unroll
            for (int np = 0; np < 4; np++) {
                uint32_t bh4[4], bl4[4];
                const uint32_t ro = (uint32_t)((warp_n0 + np*16 + offB_row)*LDSTR
                                               + kk + offB_k) * 2;
                ldmatrix_x4(bh4, bH + ro);
                ldmatrix_x4(bl4, bL + ro);
                #pragma unroll
                for (int mt = 0; mt < 2; mt++) {
                    mma16816(acc[mt][2*np],   ahf[mt], &bh4[0]);
                    mma16816(acc[mt][2*np],   ahf[mt], &bl4[0]);
                    mma16816(acc[mt][2*np],   alf[mt], &bh4[0]);
                    mma16816(acc[mt][2*np+1], ahf[mt], &bh4[2]);
                    mma16816(acc[mt][2*np+1], ahf[mt], &bl4[2]);
                    mma16816(acc[mt][2*np+1], alf[mt], &bh4[2]);
                }
            }
        }
        __syncthreads();
    }

    // ---- epilogue: bias (+Q scale), split-bf16 write, view-scramble scatter ----
    const float scale = 0.08838834764831845f;   // 1/sqrt(128)
    #pragma unroll
    for (int mt = 0; mt < 2; mt++) {
        #pragma unroll
        for (int nf = 0; nf < 8; nf++) {
            const int col = col0 + warp_n0 + nf*8 + (lane & 3)*2;
            const int h   = col >> 7;
            const int dd  = col & 127;
            const float b0 = bia[col], b1 = bia[col+1];
            #pragma unroll
            for (int half = 0; half < 2; half++) {
                const int r  = row0 + warp_m0 + mt*16 + (lane >> 2) + half*8;
                const int bp = r & 1;
                const int sp = r >> 1;
                float v0 = acc[mt][nf][half*2+0] + b0;
                float v1 = acc[mt][nf][half*2+1] + b1;
                size_t idx;
                __nv_bfloat16* ah;
                __nv_bfloat16* al;
                if (mat == 0) {
                    v0 *= scale; v1 *= scale;
                    idx = ((size_t)(bp*HEADS + h)*S_LEN + sp)*HD + dd;
                    ah = g_Qh; al = g_Ql;
                } else {
                    idx = ((size_t)(bp*HEADS + h)*SPAD + (sp + WINW))*HD + dd;
                    ah = (mat == 1) ? g_Kh : g_Vh;
                    al = (mat == 1) ? g_Kl : g_Vl;
                }
                __nv_bfloat16 h0 = __float2bfloat16(v0);
                __nv_bfloat16 h1 = __float2bfloat16(v1);
                __nv_bfloat162 hv; hv.x = h0; hv.y = h1;
                __nv_bfloat162 lv;
                lv.x = __float2bfloat16(v0 - __bfloat162float(h0));
                lv.y = __float2bfloat16(v1 - __bfloat162float(h1));
                *(__nv_bfloat162*)(ah + idx) = hv;
                *(__nv_bfloat162*)(al + idx) = lv;
            }
        }
    }
}

// ---------------------------------------------------------------------------
// Banded flash attention via mma.sync. CTA = 128 queries of one (b',h).
// 8 warps x 16 queries; 10 key chunks of 64; split-bf16 QK^T and P*V.
// ---------------------------------------------------------------------------
#define SSTR 136                       // smem row stride in bf16 (272 B)
#define QV_BYTES (128*SSTR*2)          // 34816
#define KV_BYTES (64*SSTR*2)           // 17408
#define ATT_SMEM (2*QV_BYTES + 4*KV_BYTES)   // 139264

__global__ __launch_bounds__(256) void attn_mma_kernel(float* __restrict__ out)
{
    extern __shared__ char smem[];
    const uint32_t sb = smem_to_u32(smem);
    const uint32_t sQh = sb, sQl = sb + QV_BYTES;
    const uint32_t sKh = sb + 2*QV_BYTES, sKl = sKh + KV_BYTES;
    const uint32_t sVh = sKl + KV_BYTES, sVl = sVh + KV_BYTES;

    const int s0  = blockIdx.x * 128;
    const int h   = blockIdx.y;
    const int bp  = blockIdx.z;
    const int bh  = bp*HEADS + h;
    const int tid = threadIdx.x;
    const int wid = tid >> 5;
    const int lane = tid & 31;

    const __nv_bfloat16* Qhg = g_Qh + ((size_t)bh*S_LEN + s0)*HD;
    const __nv_bfloat16* Qlg = g_Ql + ((size_t)bh*S_LEN + s0)*HD;
    const size_t kvbase = ((size_t)bh*SPAD + s0)*HD;

    // load Q tiles (hi/lo), 128 rows x 128 bf16 each
    {
        char* pQ[2] = { smem, smem + QV_BYTES };
        const __nv_bfloat16* gQ[2] = { Qhg, Qlg };
        for (int i = tid; i < 4096; i += 256) {
            int v = i >> 11, idx = i & 2047;
            int row = idx >> 4, cc = idx & 15;
            *(uint4*)(pQ[v] + row*272 + cc*16) =
                ((const uint4*)(gQ[v] + (size_t)row*HD))[cc];
        }
    }

    const int warp_q0 = wid * 16;
    const int offA_row = (lane & 7) + (lane & 8);
    const int offA_k   = (lane & 16) >> 1;
    const int offB_row = (lane & 7) + ((lane & 16) >> 1);
    const int offB_k   = lane & 8;
    // trans-ldmatrix (V) addressing
    const int vt_r = lane & 7;
    const int vt_j = ((lane >> 3) & 1) * 8;     // +8 rows for groups 1,3
    const int vt_d = ((lane >> 4) & 1) * 8;     // +8 cols for groups 2,3

    const int qlo = warp_q0 + (lane >> 2);      // tile-local query rows
    const int qhi = qlo + 8;

    float of[16][4];
    #pragma unroll
    for (int f = 0; f < 16; f++)
        of[f][0] = of[f][1] = of[f][2] = of[f][3] = 0.f;
    float m_lo = -1e30f, m_hi = -1e30f, l_lo = 0.f, l_hi = 0.f;

    for (int c = 0; c < 10; c++) {
        __syncthreads();
        // load K/V chunk (hi/lo): rows s0 + c*64 .. +63
        {
            char* pD[4] = { smem + 2*QV_BYTES, smem + 2*QV_BYTES + KV_BYTES,
                            smem + 2*QV_BYTES + 2*KV_BYTES,
                            smem + 2*QV_BYTES + 3*KV_BYTES };
            const __nv_bfloat16* gS[4] = {
                g_Kh + kvbase + (size_t)c*64*HD, g_Kl + kvbase + (size_t)c*64*HD,
                g_Vh + kvbase + (size_t)c*64*HD, g_Vl + kvbase + (size_t)c*64*HD };
            for (int i = tid; i < 4096; i += 256) {
                int v = i >> 10, idx = i & 1023;
                int row = idx >> 4, cc = idx & 15;
                *(uint4*)(pD[v] + row*272 + cc*16) =
                    ((const uint4*)(gS[v] + (size_t)row*HD))[cc];
            }
        }
        __syncthreads();

        // ---- S = Q K^T (64 keys), split-bf16, fp32 accum ----
        float sf[8][4];
        #pragma unroll
        for (int f = 0; f < 8; f++)
            sf[f][0] = sf[f][1] = sf[f][2] = sf[f][3] = 0.f;

        #pragma unroll
        for (int ks = 0; ks < 8; ks++) {
            uint32_t qh4[4], ql4[4];
            const uint32_t qo = (uint32_t)((warp_q0 + offA_row)*SSTR
                                           + ks*16 + offA_k) * 2;
            ldmatrix_x4(qh4, sQh + qo);
            ldmatrix_x4(ql4, sQl + qo);
            #pragma unroll
            for (int ng = 0; ng < 4; ng++) {
                uint32_t kh4[4], kl4[4];
                const uint32_t ko = (uint32_t)((ng*16 + offB_row)*SSTR
                                               + ks*16 + offB_k) * 2;
                ldmatrix_x4(kh4, sKh + ko);
                ldmatrix_x4(kl4, sKl + ko);
                mma16816(sf[2*ng],   qh4, &kh4[0]);
                mma16816(sf[2*ng],   qh4, &kl4[0]);
                mma16816(sf[2*ng],   ql4, &kh4[0]);
                mma16816(sf[2*ng+1], qh4, &kh4[2]);
                mma16816(sf[2*ng+1], qh4, &kl4[2]);
                mma16816(sf[2*ng+1], ql4, &kh4[2]);
            }
        }

        // ---- masked online softmax (per warp, rows qlo / qhi) ----
        const int kb = c*64 + (lane & 3)*2;
        float mxlo = -1e30f, mxhi = -1e30f;
        #pragma unroll
        for (int f = 0; f < 8; f++) {
            #pragma unroll
            for (int j = 0; j < 2; j++) {
                const int kc = kb + f*8 + j;
                const bool vlo = (kc >= qlo) && (kc <= qlo + 512);
                const bool vhi = (kc >= qhi) && (kc <= qhi + 512);
                const float slo = vlo ? sf[f][j]   : -1e30f;
                const float shi = vhi ? sf[f][2+j] : -1e30f;
                sf[f][j]   = slo;  mxlo = fmaxf(mxlo, slo);
                sf[f][2+j] = shi;  mxhi = fmaxf(mxhi, shi);
            }
        }
        mxlo = fmaxf(mxlo, __shfl_xor_sync(0xffffffffu, mxlo, 1));
        mxlo = fmaxf(mxlo, __shfl_xor_sync(0xffffffffu, mxlo, 2));
        mxhi = fmaxf(mxhi, __shfl_xor_sync(0xffffffffu, mxhi, 1));
        mxhi = fmaxf(mxhi, __shfl_xor_sync(0xffffffffu, mxhi, 2));

        const float mnlo = fmaxf(m_lo, mxlo);
        const float mnhi = fmaxf(m_hi, mxhi);
        const float alo = __expf(m_lo - mnlo);
        const float ahi = __expf(m_hi - mnhi);
        m_lo = mnlo; m_hi = mnhi;

        float sumlo = 0.f, sumhi = 0.f;
        #pragma unroll
        for (int f = 0; f < 8; f++) {
            #pragma unroll
            for (int j = 0; j < 2; j++) {
                const int kc = kb + f*8 + j;
                const bool vlo = (kc >= qlo) && (kc <= qlo + 512);
                const bool vhi = (kc >= qhi) && (kc <= qhi + 512);
                const float plo = vlo ? __expf(sf[f][j]   - mnlo) : 0.f;
                const float phi = vhi ? __expf(sf[f][2+j] - mnhi) : 0.f;
                sf[f][j] = plo;   sumlo += plo;
                sf[f][2+j] = phi; sumhi += phi;
            }
        }
        sumlo += __shfl_xor_sync(0xffffffffu, sumlo, 1);
        sumlo += __shfl_xor_sync(0xffffffffu, sumlo, 2);
        sumhi += __shfl_xor_sync(0xffffffffu, sumhi, 1);
        sumhi += __shfl_xor_sync(0xffffffffu, sumhi, 2);
        l_lo = l_lo*alo + sumlo;
        l_hi = l_hi*ahi + sumhi;

        #pragma unroll
        for (int f = 0; f < 16; f++) {
            of[f][0] *= alo; of[f][1] *= alo;
            of[f][2] *= ahi; of[f][3] *= ahi;
        }

        // ---- O += P V, split-bf16 ----
        #pragma unroll
        for (int t = 0; t < 4; t++) {
            uint32_t ah[4], al[4];
            #pragma unroll
            for (int g = 0; g < 4; g++) {
                // g: 0->(frag 2t, c0c1) 1->(frag 2t, c2c3) 2->(frag 2t+1, c0c1) 3->(2t+1, c2c3)
                const int fr = 2*t + (g >> 1);
                const int b0 = (g & 1) * 2;
                const float p0 = sf[fr][b0], p1 = sf[fr][b0+1];
                const float h0 = __bfloat162float(__float2bfloat16(p0));
                const float h1 = __bfloat162float(__float2bfloat16(p1));
                ah[g] = pack_bf16x2(h0, h1);
                al[g] = pack_bf16x2(p0 - h0, p1 - h1);
            }
            #pragma unroll
            for (int dg = 0; dg < 8; dg++) {
                uint32_t vh4[4], vl4[4];
                const uint32_t vo = (uint32_t)((t*16 + vt_j + vt_r)*SSTR
                                               + dg*16 + vt_d) * 2;
                ldmatrix_x4_trans(vh4, sVh + vo);
                ldmatrix_x4_trans(vl4, sVl + vo);
                mma16816(of[2*dg],   ah, &vh4[0]);
                mma16816(of[2*dg],   ah, &vl4[0]);
                mma16816(of[2*dg],   al, &vh4[0]);
                mma16816(of[2*dg+1], ah, &vh4[2]);
                mma16816(of[2*dg+1], ah, &vl4[2]);
                mma16816(of[2*dg+1], al, &vh4[2]);
            }
        }
    }

    // ---- write out: out[s'][b'][h*128+d] ----
    const float invlo = 1.f / l_lo;
    const float invhi = 1.f / l_hi;
    const int sqlo = s0 + qlo;
    const int sqhi = s0 + qhi;
    const size_t obase = (size_t)bp*1024 + h*128 + (lane & 3)*2;
    #pragma unroll
    for (int f = 0; f < 16; f++) {
        const int d = f*8;
        float2 o1; o1.x = of[f][0]*invlo; o1.y = of[f][1]*invlo;
        *(float2*)&out[(size_t)sqlo*2048 + obase + d] = o1;
        float2 o2; o2.x = of[f][2]*invhi; o2.y = of[f][3]*invhi;
        *(float2*)&out[(size_t)sqhi*2048 + obase + d] = o2;
    }
}

// ---------------------------------------------------------------------------
extern "C" void kernel_launch(void* const* d_in, const int* in_sizes, int n_in,
                              void* d_out, int out_size)
{
    (void)in_sizes; (void)n_in; (void)out_size;
    const float* val = (const float*)d_in[0];
    const float* Wq  = (const float*)d_in[1];
    const float* bq  = (const float*)d_in[2];
    const float* Wk  = (const float*)d_in[3];
    const float* bk  = (const float*)d_in[4];
    const float* Wv  = (const float*)d_in[5];
    const float* bv  = (const float*)d_in[6];
    float* out = (float*)d_out;

    cudaFuncSetAttribute(qkv_mma_kernel, cudaFuncAttributeMaxDynamicSharedMemorySize,
                         GEMM_SMEM);
    cudaFuncSetAttribute(attn_mma_kernel, cudaFuncAttributeMaxDynamicSharedMemorySize,
                         ATT_SMEM);

    convert_x_kernel<<<(8192*1024)/256, 256>>>(val);
    convert_w_kernel<<<(3*1024*1024)/256, 256>>>(Wq, Wk, Wv);
    {
        const int total = BATCH*HEADS * (2*WINW) * HD;
        zero_pads_kernel<<<(total + 255)/256, 256>>>();
    }
    {
        dim3 grid(1024/128, 8192/128, 3);
        qkv_mma_kernel<<<grid, 256, GEMM_SMEM>>>(bq, bk, bv);
    }
    {
        dim3 grid(S_LEN/128, HEADS, BATCH);
        attn_mma_kernel<<<grid, 256, ATT_SMEM>>>(out);
    }
}

// round 10
// speedup vs baseline: 2.9621x; 1.0620x over previous
#include <cuda_runtime.h>
#include <cuda_bf16.h>
#include <cstdint>
#include <cstddef>

#define S_LEN 4096
#define BATCH 2
#define EMB   1024
#define HEADS 8
#define HD    128
#define WINW  256
#define SPAD  (S_LEN + 2*WINW)   // 4608

// Split-bf16 Q/K/V in attention layout (written by GEMM epilogue)
__device__ __align__(16) __nv_bfloat16 g_Qh[BATCH*HEADS*S_LEN*HD];
__device__ __align__(16) __nv_bfloat16 g_Ql[BATCH*HEADS*S_LEN*HD];
__device__ __align__(16) __nv_bfloat16 g_Kh[BATCH*HEADS*SPAD*HD];
__device__ __align__(16) __nv_bfloat16 g_Kl[BATCH*HEADS*SPAD*HD];
__device__ __align__(16) __nv_bfloat16 g_Vh[BATCH*HEADS*SPAD*HD];
__device__ __align__(16) __nv_bfloat16 g_Vl[BATCH*HEADS*SPAD*HD];

// Split-bf16 GEMM inputs
__device__ __align__(16) __nv_bfloat16 g_Xh[8192*1024];
__device__ __align__(16) __nv_bfloat16 g_Xl[8192*1024];
__device__ __align__(16) __nv_bfloat16 g_Wh[3*1024*1024];
__device__ __align__(16) __nv_bfloat16 g_Wl[3*1024*1024];

// ---------------------------------------------------------------------------
// helpers
// ---------------------------------------------------------------------------
__device__ __forceinline__ uint32_t smem_to_u32(const void* p) {
    uint32_t a;
    asm("{ .reg .u64 t; cvta.to.shared.u64 t, %1; cvt.u32.u64 %0, t; }"
        : "=r"(a) : "l"(p));
    return a;
}
__device__ __forceinline__ void cp_async16(uint32_t dst, const void* src) {
    asm volatile("cp.async.cg.shared.global [%0], [%1], 16;"
                 :: "r"(dst), "l"(src) : "memory");
}
#define CP_COMMIT() asm volatile("cp.async.commit_group;" ::: "memory")
#define CP_WAIT0()  asm volatile("cp.async.wait_group 0;" ::: "memory")
#define CP_WAIT1()  asm volatile("cp.async.wait_group 1;" ::: "memory")

__device__ __forceinline__ void ldmatrix_x4(uint32_t* r, uint32_t addr) {
    asm volatile("ldmatrix.sync.aligned.m8n8.x4.shared.b16 {%0,%1,%2,%3}, [%4];"
                 : "=r"(r[0]), "=r"(r[1]), "=r"(r[2]), "=r"(r[3]) : "r"(addr));
}
__device__ __forceinline__ void ldmatrix_x4_trans(uint32_t* r, uint32_t addr) {
    asm volatile("ldmatrix.sync.aligned.m8n8.x4.trans.shared.b16 {%0,%1,%2,%3}, [%4];"
                 : "=r"(r[0]), "=r"(r[1]), "=r"(r[2]), "=r"(r[3]) : "r"(addr));
}
__device__ __forceinline__ void mma16816(float* c, const uint32_t* a,
                                         const uint32_t* b) {
    asm volatile(
        "mma.sync.aligned.m16n8k16.row.col.f32.bf16.bf16.f32 "
        "{%0,%1,%2,%3}, {%4,%5,%6,%7}, {%8,%9}, {%0,%1,%2,%3};"
        : "+f"(c[0]), "+f"(c[1]), "+f"(c[2]), "+f"(c[3])
        : "r"(a[0]), "r"(a[1]), "r"(a[2]), "r"(a[3]), "r"(b[0]), "r"(b[1]));
}
__device__ __forceinline__ uint32_t pack_bf16x2(float lo, float hi) {
    uint32_t r;
    asm("cvt.rn.bf16x2.f32 %0, %1, %2;" : "=r"(r) : "f"(hi), "f"(lo));
    return r;
}

// ---------------------------------------------------------------------------
// Split fp32 -> (bf16 hi, bf16 lo). X rows are the view-scramble gather.
// ---------------------------------------------------------------------------
__global__ void convert_x_kernel(const float* __restrict__ val)
{
    int i = blockIdx.x * blockDim.x + threadIdx.x;
    if (i >= 8192*1024) return;
    int r = i >> 10, k = i & 1023;
    int b = r >> 12, s = r & 4095;
    float f = val[s*2048 + b*1024 + k];
    __nv_bfloat16 h = __float2bfloat16(f);
    g_Xh[i] = h;
    g_Xl[i] = __float2bfloat16(f - __bfloat162float(h));
}

__global__ void convert_w_kernel(const float* __restrict__ Wq,
                                 const float* __restrict__ Wk,
                                 const float* __restrict__ Wv)
{
    int i = blockIdx.x * blockDim.x + threadIdx.x;
    if (i >= 3*1024*1024) return;
    int mat = i >> 20;
    const float* W = (mat == 0) ? Wq : (mat == 1 ? Wk : Wv);
    float f = W[i & 0xFFFFF];
    __nv_bfloat16 h = __float2bfloat16(f);
    g_Wh[i] = h;
    g_Wl[i] = __float2bfloat16(f - __bfloat162float(h));
}

// ---------------------------------------------------------------------------
// Zero the pad rows of K/V (bf16 split arrays)
// ---------------------------------------------------------------------------
__global__ void zero_pads_kernel()
{
    int i = blockIdx.x * blockDim.x + threadIdx.x;
    const int total = BATCH*HEADS * (2*WINW) * HD;
    if (i >= total) return;
    int d  = i & (HD-1);
    int t  = i >> 7;
    int jr = t & (2*WINW - 1);
    int bh = t >> 9;
    int jpad = (jr < WINW) ? jr : (S_LEN + jr);
    size_t off = ((size_t)bh*SPAD + jpad)*HD + d;
    __nv_bfloat16 z = __float2bfloat16(0.0f);
    g_Kh[off] = z; g_Kl[off] = z;
    g_Vh[off] = z; g_Vl[off] = z;
}

// ---------------------------------------------------------------------------
// Warp-MMA GEMM (unchanged from passing round)
// ---------------------------------------------------------------------------
#define BK 32
#define NKT 32                    // 1024 / 32
#define LDSTR 40                  // smem row stride in bf16 (80 B)
#define VAR_BYTES (128*LDSTR*2)   // 10240
#define STAGE_BYTES (4*VAR_BYTES) // 40960: [Ah, Al, Bh, Bl]
#define GEMM_SMEM (2*STAGE_BYTES) // 81920

__global__ __launch_bounds__(256) void qkv_mma_kernel(
    const float* __restrict__ bq, const float* __restrict__ bk,
    const float* __restrict__ bv)
{
    extern __shared__ char smem[];
    const uint32_t smem_base = smem_to_u32(smem);
    const int tid  = threadIdx.x;
    const int wid  = tid >> 5;
    const int lane = tid & 31;

    const int col0 = blockIdx.x * 128;
    const int row0 = blockIdx.y * 128;
    const int mat  = blockIdx.z;
    const float* bia = (mat == 0) ? bq : (mat == 1 ? bk : bv);

    const __nv_bfloat16* Wh = g_Wh + (size_t)mat * 1048576;
    const __nv_bfloat16* Wl = g_Wl + (size_t)mat * 1048576;

    const int ch0_row = tid >> 2,         ch0_quad = tid & 3;
    const int ch1_row = (tid + 256) >> 2, ch1_quad = (tid + 256) & 3;

    const __nv_bfloat16* srcs[4] = { g_Xh, g_Xl, Wh, Wl };
    const int vrow0[4] = { row0, row0, col0, col0 };

    const int warp_m0 = (wid & 3) * 32;
    const int warp_n0 = (wid >> 2) * 64;

    const int offA_row = (lane & 7) + (lane & 8);
    const int offA_k   = (lane & 16) >> 1;
    const int offB_row = (lane & 7) + ((lane & 16) >> 1);
    const int offB_k   = lane & 8;

    float acc[2][8][4];
    #pragma unroll
    for (int mt = 0; mt < 2; mt++)
        #pragma unroll
        for (int nf = 0; nf < 8; nf++)
            acc[mt][nf][0] = acc[mt][nf][1] = acc[mt][nf][2] = acc[mt][nf][3] = 0.f;

    {
        const uint32_t sb = smem_base;
        #pragma unroll
        for (int v = 0; v < 4; v++) {
            cp_async16(sb + v*VAR_BYTES + (ch0_row*LDSTR + ch0_quad*8)*2,
                       srcs[v] + (size_t)(vrow0[v] + ch0_row)*1024 + ch0_quad*8);
            cp_async16(sb + v*VAR_BYTES + (ch1_row*LDSTR + ch1_quad*8)*2,
                       srcs[v] + (size_t)(vrow0[v] + ch1_row)*1024 + ch1_quad*8);
        }
        CP_COMMIT();
    }

    for (int kt = 0; kt < NKT; kt++) {
        if (kt + 1 < NKT) {
            const uint32_t sb = smem_base + ((kt+1) & 1) * STAGE_BYTES;
            const int k0 = (kt+1) * BK;
            #pragma unroll
            for (int v = 0; v < 4; v++) {
                cp_async16(sb + v*VAR_BYTES + (ch0_row*LDSTR + ch0_quad*8)*2,
                           srcs[v] + (size_t)(vrow0[v] + ch0_row)*1024 + k0 + ch0_quad*8);
                cp_async16(sb + v*VAR_BYTES + (ch1_row*LDSTR + ch1_quad*8)*2,
                           srcs[v] + (size_t)(vrow0[v] + ch1_row)*1024 + k0 + ch1_quad*8);
            }
            CP_COMMIT();
            CP_WAIT1();
        } else {
            CP_WAIT0();
        }
        __syncthreads();

        const uint32_t sb = smem_base + (kt & 1) * STAGE_BYTES;
        const uint32_t aH = sb, aL = sb + VAR_BYTES;
        const uint32_t bH = sb + 2*VAR_BYTES, bL = sb + 3*VAR_BYTES;

        #pragma unroll
        for (int ks = 0; ks < 2; ks++) {
            const int kk = ks * 16;
            uint32_t ahf[2][4], alf[2][4];
            #pragma unroll
            for (int mt = 0; mt < 2; mt++) {
                const uint32_t ro = (uint32_t)((warp_m0 + mt*16 + offA_row)*LDSTR
                                               + kk + offA_k) * 2;
                ldmatrix_x4(ahf[mt], aH + ro);
                ldmatrix_x4(alf[mt], aL + ro);
            }
            #pragma unroll
            for (int np = 0; np < 4; np++) {
                uint32_t bh4[4], bl4[4];
                const uint32_t ro = (uint32_t)((warp_n0 + np*16 + offB_row)*LDSTR
                                               + kk + offB_k) * 2;
                ldmatrix_x4(bh4, bH + ro);
                ldmatrix_x4(bl4, bL + ro);
                #pragma unroll
                for (int mt = 0; mt < 2; mt++) {
                    mma16816(acc[mt][2*np],   ahf[mt], &bh4[0]);
                    mma16816(acc[mt][2*np],   ahf[mt], &bl4[0]);
                    mma16816(acc[mt][2*np],   alf[mt], &bh4[0]);
                    mma16816(acc[mt][2*np+1], ahf[mt], &bh4[2]);
                    mma16816(acc[mt][2*np+1], ahf[mt], &bl4[2]);
                    mma16816(acc[mt][2*np+1], alf[mt], &bh4[2]);
                }
            }
        }
        __syncthreads();
    }

    const float scale = 0.08838834764831845f;   // 1/sqrt(128)
    #pragma unroll
    for (int mt = 0; mt < 2; mt++) {
        #pragma unroll
        for (int nf = 0; nf < 8; nf++) {
            const int col = col0 + warp_n0 + nf*8 + (lane & 3)*2;
            const int h   = col >> 7;
            const int dd  = col & 127;
            const float b0 = bia[col], b1 = bia[col+1];
            #pragma unroll
            for (int half = 0; half < 2; half++) {
                const int r  = row0 + warp_m0 + mt*16 + (lane >> 2) + half*8;
                const int bp = r & 1;
                const int sp = r >> 1;
                float v0 = acc[mt][nf][half*2+0] + b0;
                float v1 = acc[mt][nf][half*2+1] + b1;
                size_t idx;
                __nv_bfloat16* ah;
                __nv_bfloat16* al;
                if (mat == 0) {
                    v0 *= scale; v1 *= scale;
                    idx = ((size_t)(bp*HEADS + h)*S_LEN + sp)*HD + dd;
                    ah = g_Qh; al = g_Ql;
                } else {
                    idx = ((size_t)(bp*HEADS + h)*SPAD + (sp + WINW))*HD + dd;
                    ah = (mat == 1) ? g_Kh : g_Vh;
                    al = (mat == 1) ? g_Kl : g_Vl;
                }
                __nv_bfloat16 h0 = __float2bfloat16(v0);
                __nv_bfloat16 h1 = __float2bfloat16(v1);
                __nv_bfloat162 hv; hv.x = h0; hv.y = h1;
                __nv_bfloat162 lv;
                lv.x = __float2bfloat16(v0 - __bfloat162float(h0));
                lv.y = __float2bfloat16(v1 - __bfloat162float(h1));
                *(__nv_bfloat162*)(ah + idx) = hv;
                *(__nv_bfloat162*)(al + idx) = lv;
            }
        }
    }
}

// ---------------------------------------------------------------------------
// Banded flash attention via mma.sync, v2:
//  - Q fragments cached in registers across all chunks (1 CTA/SM => 256 regs)
//  - KV chunks double-buffered with cp.async (load latency hidden)
// CTA = 128 queries of one (b',h); 8 warps x 16 queries; 10 chunks of 64 keys.
// ---------------------------------------------------------------------------
#define SSTR 136                       // smem row stride in bf16 (272 B)
#define QV_BYTES (128*SSTR*2)          // 34816 per Q var
#define KV_VAR   (64*SSTR*2)           // 17408 per KV var
#define KV_STAGE (4*KV_VAR)            // 69632: [Kh, Kl, Vh, Vl]
#define ATT_SMEM (2*QV_BYTES + 2*KV_STAGE)   // 208896

__global__ __launch_bounds__(256, 1) void attn_mma_kernel(float* __restrict__ out)
{
    extern __shared__ char smem[];
    const uint32_t sb = smem_to_u32(smem);
    const uint32_t sQh = sb, sQl = sb + QV_BYTES;
    const uint32_t sKV = sb + 2*QV_BYTES;     // two stages of [Kh,Kl,Vh,Vl]

    const int s0  = blockIdx.x * 128;
    const int h   = blockIdx.y;
    const int bp  = blockIdx.z;
    const int bh  = bp*HEADS + h;
    const int tid = threadIdx.x;
    const int wid = tid >> 5;
    const int lane = tid & 31;

    const __nv_bfloat16* Qhg = g_Qh + ((size_t)bh*S_LEN + s0)*HD;
    const __nv_bfloat16* Qlg = g_Ql + ((size_t)bh*S_LEN + s0)*HD;
    const size_t kvbase = ((size_t)bh*SPAD + s0)*HD;
    const __nv_bfloat16* gKV[4] = {
        g_Kh + kvbase, g_Kl + kvbase, g_Vh + kvbase, g_Vl + kvbase };

    // stage Q via cp.async (group 0)
    #pragma unroll
    for (int t = 0; t < 16; t++) {
        const int i = tid + t*256;          // 0..4095
        const int v = i >> 11, idx = i & 2047;
        const int row = idx >> 4, ch = idx & 15;
        cp_async16((v ? sQl : sQh) + row*272 + ch*16,
                   (v ? Qlg : Qhg) + (size_t)row*HD + ch*8);
    }
    CP_COMMIT();

    // prefetch KV chunk 0 into stage 0 (group 1)
    #pragma unroll
    for (int t = 0; t < 16; t++) {
        const int i = tid + t*256;
        const int v = i >> 10, idx = i & 1023;
        const int row = idx >> 4, ch = idx & 15;
        cp_async16(sKV + v*KV_VAR + row*272 + ch*16,
                   gKV[v] + (size_t)row*HD + ch*8);
    }
    CP_COMMIT();

    const int warp_q0 = wid * 16;
    const int offA_row = (lane & 7) + (lane & 8);
    const int offA_k   = (lane & 16) >> 1;
    const int offB_row = (lane & 7) + ((lane & 16) >> 1);
    const int offB_k   = lane & 8;
    const int vt_r = lane & 7;
    const int vt_j = ((lane >> 3) & 1) * 8;
    const int vt_d = ((lane >> 4) & 1) * 8;

    const int qlo = warp_q0 + (lane >> 2);
    const int qhi = qlo + 8;

    CP_WAIT1();            // Q ready (chunk 0 may still be in flight)
    __syncthreads();

    // cache Q fragments in registers for all 8 k-steps
    uint32_t qh[8][4], ql[8][4];
    #pragma unroll
    for (int ks = 0; ks < 8; ks++) {
        const uint32_t qo = (uint32_t)((warp_q0 + offA_row)*SSTR
                                       + ks*16 + offA_k) * 2;
        ldmatrix_x4(qh[ks], sQh + qo);
        ldmatrix_x4(ql[ks], sQl + qo);
    }

    float of[16][4];
    #pragma unroll
    for (int f = 0; f < 16; f++)
        of[f][0] = of[f][1] = of[f][2] = of[f][3] = 0.f;
    float m_lo = -1e30f, m_hi = -1e30f, l_lo = 0.f, l_hi = 0.f;

    for (int c = 0; c < 10; c++) {
        // prefetch chunk c+1 into the other stage
        if (c < 9) {
            const uint32_t dstS = sKV + ((c+1) & 1) * KV_STAGE;
            const size_t srcOff = (size_t)(c+1)*64*HD;
            #pragma unroll
            for (int t = 0; t < 16; t++) {
                const int i = tid + t*256;
                const int v = i >> 10, idx = i & 1023;
                const int row = idx >> 4, ch = idx & 15;
                cp_async16(dstS + v*KV_VAR + row*272 + ch*16,
                           gKV[v] + srcOff + (size_t)row*HD + ch*8);
            }
            CP_COMMIT();
            CP_WAIT1();        // chunk c complete
        } else {
            CP_WAIT0();
        }
        __syncthreads();

        const uint32_t stg = sKV + (c & 1) * KV_STAGE;
        const uint32_t cKh = stg, cKl = stg + KV_VAR;
        const uint32_t cVh = stg + 2*KV_VAR, cVl = stg + 3*KV_VAR;

        // ---- S = Q K^T (64 keys), split-bf16, fp32 accum ----
        float sf[8][4];
        #pragma unroll
        for (int f = 0; f < 8; f++)
            sf[f][0] = sf[f][1] = sf[f][2] = sf[f][3] = 0.f;

        #pragma unroll
        for (int ks = 0; ks < 8; ks++) {
            #pragma unroll
            for (int ng = 0; ng < 4; ng++) {
                uint32_t kh4[4], kl4[4];
                const uint32_t ko = (uint32_t)((ng*16 + offB_row)*SSTR
                                               + ks*16 + offB_k) * 2;
                ldmatrix_x4(kh4, cKh + ko);
                ldmatrix_x4(kl4, cKl + ko);
                mma16816(sf[2*ng],   qh[ks], &kh4[0]);
                mma16816(sf[2*ng],   qh[ks], &kl4[0]);
                mma16816(sf[2*ng],   ql[ks], &kh4[0]);
                mma16816(sf[2*ng+1], qh[ks], &kh4[2]);
                mma16816(sf[2*ng+1], qh[ks], &kl4[2]);
                mma16816(sf[2*ng+1], ql[ks], &kh4[2]);
            }
        }

        // ---- masked online softmax ----
        const int kb = c*64 + (lane & 3)*2;
        float mxlo = -1e30f, mxhi = -1e30f;
        #pragma unroll
        for (int f = 0; f < 8; f++) {
            #pragma unroll
            for (int j = 0; j < 2; j++) {
                const int kc = kb + f*8 + j;
                const bool vlo = (kc >= qlo) && (kc <= qlo + 512);
                const bool vhi = (kc >= qhi) && (kc <= qhi + 512);
                const float slo = vlo ? sf[f][j]   : -1e30f;
                const float shi = vhi ? sf[f][2+j] : -1e30f;
                sf[f][j]   = slo;  mxlo = fmaxf(mxlo, slo);
                sf[f][2+j] = shi;  mxhi = fmaxf(mxhi, shi);
            }
        }
        mxlo = fmaxf(mxlo, __shfl_xor_sync(0xffffffffu, mxlo, 1));
        mxlo = fmaxf(mxlo, __shfl_xor_sync(0xffffffffu, mxlo, 2));
        mxhi = fmaxf(mxhi, __shfl_xor_sync(0xffffffffu, mxhi, 1));
        mxhi = fmaxf(mxhi, __shfl_xor_sync(0xffffffffu, mxhi, 2));

        const float mnlo = fmaxf(m_lo, mxlo);
        const float mnhi = fmaxf(m_hi, mxhi);
        const float alo = __expf(m_lo - mnlo);
        const float ahi = __expf(m_hi - mnhi);
        m_lo = mnlo; m_hi = mnhi;

        float sumlo = 0.f, sumhi = 0.f;
        #pragma unroll
        for (int f = 0; f < 8; f++) {
            #pragma unroll
            for (int j = 0; j < 2; j++) {
                const int kc = kb + f*8 + j;
                const bool vlo = (kc >= qlo) && (kc <= qlo + 512);
                const bool vhi = (kc >= qhi) && (kc <= qhi + 512);
                const float plo = vlo ? __expf(sf[f][j]   - mnlo) : 0.f;
                const float phi = vhi ? __expf(sf[f][2+j] - mnhi) : 0.f;
                sf[f][j] = plo;   sumlo += plo;
                sf[f][2+j] = phi; sumhi += phi;
            }
        }
        sumlo += __shfl_xor_sync(0xffffffffu, sumlo, 1);
        sumlo += __shfl_xor_sync(0xffffffffu, sumlo, 2);
        sumhi += __shfl_xor_sync(0xffffffffu, sumhi, 1);
        sumhi += __shfl_xor_sync(0xffffffffu, sumhi, 2);
        l_lo = l_lo*alo + sumlo;
        l_hi = l_hi*ahi + sumhi;

        #pragma unroll
        for (int f = 0; f < 16; f++) {
            of[f][0] *= alo; of[f][1] *= alo;
            of[f][2] *= ahi; of[f][3] *= ahi;
        }

        // ---- O += P V, split-bf16 ----
        #pragma unroll
        for (int t = 0; t < 4; t++) {
            uint32_t ah[4], al[4];
            #pragma unroll
            for (int g = 0; g < 4; g++) {
                const int fr = 2*t + (g >> 1);
                const int b0 = (g & 1) * 2;
                const float p0 = sf[fr][b0], p1 = sf[fr][b0+1];
                const float h0 = __bfloat162float(__float2bfloat16(p0));
                const float h1 = __bfloat162float(__float2bfloat16(p1));
                ah[g] = pack_bf16x2(h0, h1);
                al[g] = pack_bf16x2(p0 - h0, p1 - h1);
            }
            #pragma unroll
            for (int dg = 0; dg < 8; dg++) {
                uint32_t vh4[4], vl4[4];
                const uint32_t vo = (uint32_t)((t*16 + vt_j + vt_r)*SSTR
                                               + dg*16 + vt_d) * 2;
                ldmatrix_x4_trans(vh4, cVh + vo);
                ldmatrix_x4_trans(vl4, cVl + vo);
                mma16816(of[2*dg],   ah, &vh4[0]);
                mma16816(of[2*dg],   ah, &vl4[0]);
                mma16816(of[2*dg],   al, &vh4[0]);
                mma16816(of[2*dg+1], ah, &vh4[2]);
                mma16816(of[2*dg+1], ah, &vl4[2]);
                mma16816(of[2*dg+1], al, &vh4[2]);
            }
        }
        __syncthreads();
    }

    // ---- write out: out[s'][b'][h*128+d] ----
    const float invlo = 1.f / l_lo;
    const float invhi = 1.f / l_hi;
    const int sqlo = s0 + qlo;
    const int sqhi = s0 + qhi;
    const size_t obase = (size_t)bp*1024 + h*128 + (lane & 3)*2;
    #pragma unroll
    for (int f = 0; f < 16; f++) {
        const int d = f*8;
        float2 o1; o1.x = of[f][0]*invlo; o1.y = of[f][1]*invlo;
        *(float2*)&out[(size_t)sqlo*2048 + obase + d] = o1;
        float2 o2; o2.x = of[f][2]*invhi; o2.y = of[f][3]*invhi;
        *(float2*)&out[(size_t)sqhi*2048 + obase + d] = o2;
    }
}

// ---------------------------------------------------------------------------
extern "C" void kernel_launch(void* const* d_in, const int* in_sizes, int n_in,
                              void* d_out, int out_size)
{
    (void)in_sizes; (void)n_in; (void)out_size;
    const float* val = (const float*)d_in[0];
    const float* Wq  = (const float*)d_in[1];
    const float* bq  = (const float*)d_in[2];
    const float* Wk  = (const float*)d_in[3];
    const float* bk  = (const float*)d_in[4];
    const float* Wv  = (const float*)d_in[5];
    const float* bv  = (const float*)d_in[6];
    float* out = (float*)d_out;

    cudaFuncSetAttribute(qkv_mma_kernel, cudaFuncAttributeMaxDynamicSharedMemorySize,
                         GEMM_SMEM);
    cudaFuncSetAttribute(attn_mma_kernel, cudaFuncAttributeMaxDynamicSharedMemorySize,
                         ATT_SMEM);

    convert_x_kernel<<<(8192*1024)/256, 256>>>(val);
    convert_w_kernel<<<(3*1024*1024)/256, 256>>>(Wq, Wk, Wv);
    {
        const int total = BATCH*HEADS * (2*WINW) * HD;
        zero_pads_kernel<<<(total + 255)/256, 256>>>();
    }
    {
        dim3 grid(1024/128, 8192/128, 3);
        qkv_mma_kernel<<<grid, 256, GEMM_SMEM>>>(bq, bk, bv);
    }
    {
        dim3 grid(S_LEN/128, HEADS, BATCH);
        attn_mma_kernel<<<grid, 256, ATT_SMEM>>>(out);
    }
}